// round 13
// baseline (speedup 1.0000x reference)
#include <cuda_runtime.h>
#include <cuda_bf16.h>

// Problem constants (fixed by the problem spec)
#define NS        4096
#define NQ_TOTAL  32768     // B * N_Q
#define KNN       8
#define FDIM      256
#define FDIM4     (FDIM/4)

// Grid parameters: 20^3 cells of 0.44 over [-4.4, 4.4] (coords are N(0,1);
// out-of-range points clamp to boundary cells -- bound logic accounts for it)
#define NC        20
#define NCELL     (NC*NC*NC)      // 8000
#define CS        0.44f
#define GLO       (-4.4f)
#define CAP       1024            // u64 candidate slots per warp
#define WARPS     8
#define QTHREADS  256
#define SCAN_T    1024
#define SCAN_C    8               // cells per scan thread (1024*8 >= 8000)

typedef unsigned long long ull;

// Device scratch (globals: allowed; no allocation)
__device__ int    g_cnt   [NCELL];
__device__ int    g_startc[NCELL + 1];
__device__ int    g_cur   [NCELL];
__device__ int    g_cellid[NS];
__device__ float4 g_ss    [NS];      // cell-sorted sensors (x, y, z, -0.5*|s|^2)
__device__ int    g_so    [NS];      // cell-sorted original index
__device__ float  g_w     [NQ_TOTAL * KNN];
__device__ int    g_idx   [NQ_TOTAL * KNN];

// ---- u64 key: larger key == (larger t, then smaller original index) ----
__device__ __forceinline__ ull pack_key(float t, int orig)
{
    unsigned b   = __float_as_uint(t);
    unsigned key = b ^ (unsigned)(((int)b >> 31) | 0x80000000);  // monotonic in t
    return ((ull)key << 32) | (unsigned)(~orig);
}
__device__ __forceinline__ float decode_t(ull k)
{
    unsigned key = (unsigned)(k >> 32);
    unsigned b   = (key & 0x80000000u) ? (key ^ 0x80000000u) : ~key;
    return __uint_as_float(b);
}

// Branchless sorted-8 insert of key x, descending (slow path only)
__device__ __forceinline__ void kins(ull x, ull (&v)[KNN])
{
#pragma unroll
    for (int j = KNN - 1; j >= 1; --j) {
        bool pjm = x > v[j-1];
        bool pj  = x > v[j];
        v[j] = pjm ? v[j-1] : (pj ? x : v[j]);
    }
    v[0] = (x > v[0]) ? x : v[0];
}

// ---------------------------------------------------------------------------
// Build kernels
// ---------------------------------------------------------------------------
__global__ void kzero()
{
    int i = blockIdx.x * 256 + threadIdx.x;
    if (i < NCELL) g_cnt[i] = 0;
}

__device__ __forceinline__ int clampc(float v)
{
    return min(NC - 1, max(0, (int)floorf((v - GLO) / CS)));
}

__global__ void kbin(const float* __restrict__ sc)
{
    int i = blockIdx.x * 256 + threadIdx.x;   // grid sized exactly to NS
    int c = (clampc(sc[3*i+2]) * NC + clampc(sc[3*i+1])) * NC + clampc(sc[3*i+0]);
    g_cellid[i] = c;
    atomicAdd(&g_cnt[c], 1);
}

__global__ void __launch_bounds__(SCAN_T) kscan()
{
    __shared__ int sh[SCAN_T];
    const int t  = threadIdx.x;
    const int c0 = t * SCAN_C;

    int a[SCAN_C];
    int s = 0;
#pragma unroll
    for (int j = 0; j < SCAN_C; j++) {
        int c = c0 + j;
        a[j] = (c < NCELL) ? g_cnt[c] : 0;
        s += a[j];
    }
    sh[t] = s;
    __syncthreads();
    for (int off = 1; off < SCAN_T; off <<= 1) {
        int v = (t >= off) ? sh[t - off] : 0;
        __syncthreads();
        sh[t] += v;
        __syncthreads();
    }
    int excl = sh[t] - s;
#pragma unroll
    for (int j = 0; j < SCAN_C; j++) {
        int c = c0 + j;
        if (c < NCELL) { g_startc[c] = excl; g_cur[c] = excl; }
        excl += a[j];
    }
    if (t == SCAN_T - 1) g_startc[NCELL] = sh[SCAN_T - 1];
}

__global__ void kscatter(const float* __restrict__ sc)
{
    int i = blockIdx.x * 256 + threadIdx.x;
    int p = atomicAdd(&g_cur[g_cellid[i]], 1);
    float x = sc[3*i+0], y = sc[3*i+1], z = sc[3*i+2];
    g_ss[p] = make_float4(x, y, z, -0.5f * (x*x + y*y + z*z));
    g_so[p] = i;
}

// ---------------------------------------------------------------------------
// Query kernel: one warp per query. Grid-pruned candidates scored into a
// per-warp smem key buffer; exact top-8 via 8x warp-argmax over unique keys.
// Conservative face-distance bound; k=1 -> k=2 -> exact full-scan cascade.
// IDW weights fused (exact distances from original coords, no cancellation).
// ---------------------------------------------------------------------------
__global__ void __launch_bounds__(QTHREADS) kquery(const float* __restrict__ qc,
                                                   const float* __restrict__ sc)
{
    extern __shared__ ull K[];                 // WARPS * CAP * 8B = 64 KB
    const int wid  = threadIdx.x >> 5;
    const int lane = threadIdx.x & 31;
    const int q    = blockIdx.x * WARPS + wid;
    ull* KW = K + wid * CAP;

    const float qx = qc[3*q+0], qy = qc[3*q+1], qz = qc[3*q+2];
    const float q2 = qx*qx + qy*qy + qz*qz;
    const int cx = clampc(qx), cy = clampc(qy), cz = clampc(qz);

    ull  top[KNN];
    bool done = false;

    for (int k = 1; k <= 2 && !done; k++) {
        const int xlo = max(cx-k, 0), xhi = min(cx+k, NC-1);
        const int ylo = max(cy-k, 0), yhi = min(cy+k, NC-1);
        const int zlo = max(cz-k, 0), zhi = min(cz+k, NC-1);

        int  ncand = 0;
        bool ov    = false;

        for (int z = zlo; z <= zhi && !ov; z++) {
            for (int y = ylo; y <= yhi && !ov; y++) {
                const int rowb   = (z * NC + y) * NC;
                const int pstart = g_startc[rowb + xlo];
                const int pend   = g_startc[rowb + xhi + 1];
                for (int p = pstart; p < pend; p += 32) {
                    if (ncand + 32 > CAP) { ov = true; break; }
                    const int count = min(32, pend - p);
                    if (lane < count) {
                        const int i = p + lane;
                        float4 s = g_ss[i];
                        float  t = fmaf(qx, s.x, fmaf(qy, s.y, fmaf(qz, s.z, s.w)));
                        KW[ncand + lane] = pack_key(t, g_so[i]);
                    }
                    ncand += count;
                }
            }
        }
        if (ov) break;    // fall through to exact slow path

        const int R = (ncand + 31) >> 5;       // rows of 32 (warp-uniform)
        if (ncand + lane < R * 32) KW[ncand + lane] = 0;   // pad tail
        __syncwarp();

        // 8x warp-argmax (keys unique -> exactly one winner slot per pass)
        for (int it = 0; it < KNN; it++) {
            ull lm = 0; int ls = -1;
            for (int r = 0; r < R; r++) {
                ull v = KW[r * 32 + lane];
                if (v > lm) { lm = v; ls = r; }
            }
            ull m = lm;
            for (int o = 16; o; o >>= 1) {
                ull x = __shfl_xor_sync(0xffffffffu, m, o);
                m = (x > m) ? x : m;
            }
            if (m != 0 && lm == m) KW[ls * 32 + lane] = 0;
            top[it] = m;
            __syncwarp();
        }

        if (top[KNN-1] != 0ULL) {
            // Bound: every unsearched sensor lies beyond a non-boundary face.
            float t8   = decode_t(top[KNN-1]);
            float d8sq = fmaxf(fmaf(-2.0f, t8, q2), 0.0f);
            float D = 1e30f;
            if (xlo > 0)     D = fminf(D, qx - (GLO + xlo * CS));
            if (xhi < NC-1)  D = fminf(D, (GLO + (xhi + 1) * CS) - qx);
            if (ylo > 0)     D = fminf(D, qy - (GLO + ylo * CS));
            if (yhi < NC-1)  D = fminf(D, (GLO + (yhi + 1) * CS) - qy);
            if (zlo > 0)     D = fminf(D, qz - (GLO + zlo * CS));
            if (zhi < NC-1)  D = fminf(D, (GLO + (zhi + 1) * CS) - qz);
            float Dm = D - 1e-3f;
            if (Dm > 0.0f && d8sq <= Dm * Dm) done = true;
        }
    }

    if (!done) {
        // Exact full scan: per-lane sorted-8 keys, then the same 8x argmax merge
        ull v[KNN];
#pragma unroll
        for (int j = 0; j < KNN; j++) v[j] = 0;
        for (int i = lane; i < NS; i += 32) {
            float4 s = g_ss[i];
            float  t = fmaf(qx, s.x, fmaf(qy, s.y, fmaf(qz, s.z, s.w)));
            ull kk = pack_key(t, g_so[i]);
            if (kk > v[KNN-1]) kins(kk, v);
        }
#pragma unroll
        for (int j = 0; j < KNN; j++) KW[j * 32 + lane] = v[j];
        __syncwarp();
        for (int it = 0; it < KNN; it++) {
            ull lm = 0; int ls = -1;
            for (int r = 0; r < KNN; r++) {
                ull vv = KW[r * 32 + lane];
                if (vv > lm) { lm = vv; ls = r; }
            }
            ull m = lm;
            for (int o = 16; o; o >>= 1) {
                ull x = __shfl_xor_sync(0xffffffffu, m, o);
                m = (x > m) ? x : m;
            }
            if (m != 0 && lm == m) KW[ls * 32 + lane] = 0;
            top[it] = m;
            __syncwarp();
        }
    }

    // IDW weights from exact original coords (no cancellation), lanes 0..7
    float w    = 0.0f;
    int   orig = 0;
    if (lane < KNN) {
        orig = (int)(~(unsigned)top[lane]);
        float dx = qx - sc[3*orig+0];
        float dy = qy - sc[3*orig+1];
        float dz = qz - sc[3*orig+2];
        float d  = sqrtf(fmaf(dx, dx, fmaf(dy, dy, dz*dz)));
        w = 1.0f / (d + 1e-8f);
    }
    float ws = w;
    ws += __shfl_xor_sync(0xffffffffu, ws, 1, 8);
    ws += __shfl_xor_sync(0xffffffffu, ws, 2, 8);
    ws += __shfl_xor_sync(0xffffffffu, ws, 4, 8);
    if (lane < KNN) {
        g_w  [q * KNN + lane] = w / ws;
        g_idx[q * KNN + lane] = orig;
    }
}

// ---------------------------------------------------------------------------
// Gather kernel: weighted feature gather. One warp per query, coalesced float4.
// (At the L2 roofline: 268 MB of L2-resident reads ~ 21 us.)
// ---------------------------------------------------------------------------
__global__ void __launch_bounds__(256) gather_kernel(const float* __restrict__ feats,
                                                     float* __restrict__ out)
{
    const int gw   = (blockIdx.x * 256 + threadIdx.x) >> 5;  // global query id
    const int lane = threadIdx.x & 31;
    const int b    = gw >> 13;                               // / 8192

    const float4* __restrict__ fb =
        reinterpret_cast<const float4*>(feats) + (size_t)b * NS * FDIM4;

    float4 a0 = make_float4(0.f, 0.f, 0.f, 0.f);
    float4 a1 = make_float4(0.f, 0.f, 0.f, 0.f);

#pragma unroll
    for (int k = 0; k < KNN; k++) {
        const float wk = g_w  [gw*KNN + k];   // same addr across warp -> broadcast
        const int   id = g_idx[gw*KNN + k];
        const float4* __restrict__ fr = fb + (size_t)id * FDIM4;
        float4 f0 = fr[lane];
        float4 f1 = fr[lane + 32];
        a0.x = fmaf(wk, f0.x, a0.x); a0.y = fmaf(wk, f0.y, a0.y);
        a0.z = fmaf(wk, f0.z, a0.z); a0.w = fmaf(wk, f0.w, a0.w);
        a1.x = fmaf(wk, f1.x, a1.x); a1.y = fmaf(wk, f1.y, a1.y);
        a1.z = fmaf(wk, f1.z, a1.z); a1.w = fmaf(wk, f1.w, a1.w);
    }

    float4* __restrict__ o = reinterpret_cast<float4*>(out) + (size_t)gw * FDIM4;
    o[lane]      = a0;
    o[lane + 32] = a1;
}

// ---------------------------------------------------------------------------
// Launch: six dependent kernels, graph-capturable, allocation-free.
// ---------------------------------------------------------------------------
extern "C" void kernel_launch(void* const* d_in, const int* in_sizes, int n_in,
                              void* d_out, int out_size)
{
    const float* qc = (const float*)d_in[0];   // query_coords   (B, NQ, 3)
    const float* sc = (const float*)d_in[1];   // sensor_coords  (NS, 3)
    const float* ft = (const float*)d_in[2];   // sensor_features(B, NS, F)

    const int qsmem = WARPS * CAP * 8;         // 64 KB

    cudaFuncSetAttribute(kquery,
                         cudaFuncAttributeMaxDynamicSharedMemorySize, qsmem);

    kzero        <<<(NCELL + 255) / 256, 256>>>();
    kbin         <<<NS / 256, 256>>>(sc);
    kscan        <<<1, SCAN_T>>>();
    kscatter     <<<NS / 256, 256>>>(sc);
    kquery       <<<NQ_TOTAL / WARPS, QTHREADS, qsmem>>>(qc, sc);
    gather_kernel<<<(NQ_TOTAL * 32) / 256, 256>>>(ft, (float*)d_out);
}